// round 7
// baseline (speedup 1.0000x reference)
#include <cuda_runtime.h>
#include <cstdint>
#include <cstddef>

// Bihomogeneous_k3 — warp-per-row, fused re+im, aligned re-stores (phase
// schedule), and closed-form p = floor((71 - sqrt(5041-8s))/2) via MUFU
// (exact: 5041-8*off(p) is a perfect square; +0.005 bias absorbs approx err).

#define NVAR 5
#define NM 35
#define NPAIR 630
#define NCOL 1225
#define WPB 8
#define NGRP 20

template<int... I> struct iseq {};
template<int N, int... I> struct make_iseq : make_iseq<N - 1, N - 1, I...> {};
template<int... I> struct make_iseq<0, I...> { using type = iseq<I...>; };

__device__ __forceinline__ float fsqrt_approx(float x) {
    float r;
    asm("sqrt.approx.f32 %0, %1;" : "=f"(r) : "f"(x));
    return r;
}

template<int G>
__device__ __forceinline__ void do_group(const float2* __restrict__ zz,
                                         float* __restrict__ orow,
                                         float* __restrict__ orowi,
                                         int c0, float c0f, int lane) {
    const int s = c0 + 32 * G + lane;          // c0 in [0,31]: aligned schedule
    if constexpr (32 * G + 62 >= NPAIR) {      // only trailing groups need guard
        if (s >= NPAIR) return;
    }
    // p = floor((71 - sqrt(5041 - 8s))/2 + bias)   (MUFU + FFMA + F2I pipes)
    const float sf  = c0f + (float)(32 * G);           // exact integer float
    const float arg = fmaf(-8.0f, sf, 5041.0f);        // >= 9 for valid s
    const int   p   = (int)fmaf(-0.5f, fsqrt_approx(arg), 35.505f);
    const int   off = (p * (71 - p)) >> 1;
    const int   q   = s + p - off;

    const float2 a = zz[p];                    // broadcast: 1 wf
    const float2 b = zz[q];                    // consecutive q: 2 wf
    __stcs(orow + s, a.x * b.x + a.y * b.y);   // 128B-aligned: 1 wf
    if (q > p)                                 // strict pair -> im column
        __stcs(orowi + (s - p), a.y * b.x - a.x * b.y);
}

template<int... G>
__device__ __forceinline__ void all_groups(iseq<G...>, const float2* __restrict__ zz,
                                           float* __restrict__ orow,
                                           float* __restrict__ orowi,
                                           int c0, float c0f, int lane) {
    (do_group<G>(zz, orow, orowi, c0, c0f, lane), ...);
}

// monomial index table for stage 1 (2 warp-iterations, negligible traffic)
struct TabM { ushort ijk[40]; };
static constexpr TabM make_tabm() {
    TabM t{};
    int m = 0;
    for (int i = 0; i < NVAR; i++)
        for (int j = i; j < NVAR; j++)
            for (int k = j; k < NVAR; k++) {
                t.ijk[m] = (ushort)(i | (j << 4) | (k << 8));
                m++;
            }
    return t;
}
__device__ const TabM g_tabm = make_tabm();

__global__ void __launch_bounds__(WPB * 32)
bihom_k3_kernel(const float* __restrict__ z_re,
                const float* __restrict__ z_im,
                float* __restrict__ out, int B)
{
    const int warp = threadIdx.x >> 5;
    const int lane = threadIdx.x & 31;
    const int row  = blockIdx.x * WPB + warp;

    __shared__ float2 szz[WPB][NM + 1];
    __shared__ float  sz[WPB][2][NVAR + 3];

    if (row >= B) return;   // one row per warp: uniform exit

    // stage 0: row inputs into smem
    if (lane < NVAR) {
        sz[warp][0][lane] = z_re[row * NVAR + lane];
        sz[warp][1][lane] = z_im[row * NVAR + lane];
    }
    __syncwarp();

    // stage 1: 35 complex monomials z_i z_j z_k
    for (int mm = lane; mm < NM; mm += 32) {
        const unsigned v = g_tabm.ijk[mm];
        const int i = v & 15, j = (v >> 4) & 15, k = (v >> 8) & 15;
        const float ar = sz[warp][0][i], ai = sz[warp][1][i];
        const float br = sz[warp][0][j], bi = sz[warp][1][j];
        const float cr = sz[warp][0][k], ci = sz[warp][1][k];
        const float tr = ar * br - ai * bi;
        const float ti = ar * bi + ai * br;
        szz[warp][mm] = make_float2(tr * cr - ti * ci, tr * ci + ti * cr);
    }
    __syncwarp();

    // stage 2: phase so that (row*NCOL + c0) is 128B-aligned
    const int rowoff = row * NCOL;
    const int c0 = (-rowoff) & 31;
    const float c0f = (float)(c0 + lane);

    float* __restrict__ orow  = out + (size_t)rowoff;
    float* __restrict__ orowi = orow + (NPAIR - 1);   // im col = 629 + s - p
    const float2* zz = szz[warp];

    // prologue: columns [0, c0). Here s < 31 < off(1)=35 -> p = 0, q = s.
    {
        const int s0 = c0 - 32 + lane;
        if (s0 >= 0) {
            const float2 a = zz[0];
            const float2 b = zz[s0];
            __stcs(orow + s0, a.x * b.x + a.y * b.y);
            if (s0 > 0)
                __stcs(orowi + s0, a.y * b.x - a.x * b.y);
        }
    }

    all_groups(typename make_iseq<NGRP>::type{}, zz, orow, orowi, c0, c0f, lane);
}

extern "C" void kernel_launch(void* const* d_in, const int* in_sizes, int n_in,
                              void* d_out, int out_size) {
    const float* z_re = (const float*)d_in[0];
    const float* z_im = (const float*)d_in[1];
    float* out = (float*)d_out;
    const int B = in_sizes[0] / NVAR;
    const int grid = (B + WPB - 1) / WPB;
    bihom_k3_kernel<<<grid, WPB * 32>>>(z_re, z_im, out, B);
}